// round 13
// baseline (speedup 1.0000x reference)
#include <cuda_runtime.h>
#include <cuda_bf16.h>
#include <cstdint>

// ============================================================================
// Compile-time construction of the conjugator matrices
//   G_l = Re(Q^H * P * d(pi/2) * Q)
// Every matrix element becomes a SASS immediate (FFMA src1-imm, rt=1) and
// structural zeros are deleted at compile time.
// ============================================================================

__host__ __device__ constexpr double csqrt_c(double x) {
    if (x <= 0.0) return 0.0;
    double s = 1.0;
    while (x > 4.0)  { x *= 0.25; s *= 2.0; }
    while (x < 0.25) { x *= 4.0;  s *= 0.5; }
    double g = 1.0;
    for (int i = 0; i < 30; i++) g = 0.5 * (g + x / g);
    return s * g;
}

struct GMatT {
    double g[169];
    __host__ __device__ constexpr GMatT(int l) : g{} {
        double fact[14] = {};
        fact[0] = 1.0;
        for (int i = 1; i < 14; i++) fact[i] = fact[i - 1] * (double)i;
        const int n = 2 * l + 1;
        double dmat[169] = {}, Qre[169] = {}, Qim[169] = {};
        double T2re[169] = {}, T2im[169] = {};
        double scale = 1.0;
        for (int i = 0; i < l; i++) scale *= 0.5;   // 2^-l

        for (int i = 0; i < n; i++)
            for (int j = 0; j < n; j++) {
                int mp = i - l, m = j - l;
                double pref = csqrt_c(fact[l + mp] * fact[l - mp] *
                                      fact[l + m] * fact[l - m]);
                int smin = (m - mp > 0) ? (m - mp) : 0;
                int smax = (l + m < l - mp) ? (l + m) : (l - mp);
                double sum = 0.0;
                for (int s = smin; s <= smax; s++) {
                    double term = 1.0 / (fact[l + m - s] * fact[s] *
                                         fact[mp - m + s] * fact[l - mp - s]);
                    sum += ((mp - m + s) & 1) ? -term : term;
                }
                dmat[i * n + j] = pref * sum * scale;
            }
        const double irt2 = 0.70710678118654752440084436210485;
        for (int m = -l; m < 0; m++) {
            Qre[(l + m) * n + (l - m)] = irt2;
            Qim[(l + m) * n + (l + m)] = -irt2;
        }
        Qre[l * n + l] = 1.0;
        for (int m = 1; m <= l; m++) {
            double sgn = (m & 1) ? -1.0 : 1.0;
            Qre[(l + m) * n + (l + m)] = sgn * irt2;
            Qim[(l + m) * n + (l - m)] = sgn * irt2;
        }
        for (int i = 0; i < n; i++) {
            int mp = i - l;
            int ph = ((mp % 4) + 4) % 4;
            double pre = (ph == 0) ? 1.0 : ((ph == 2) ? -1.0 : 0.0);
            double pim = (ph == 1) ? -1.0 : ((ph == 3) ? 1.0 : 0.0);
            for (int b = 0; b < n; b++) {
                double sre = 0.0, sim = 0.0;
                for (int k = 0; k < n; k++) {
                    double t = dmat[i * n + k];
                    sre += t * Qre[k * n + b];
                    sim += t * Qim[k * n + b];
                }
                T2re[i * n + b] = pre * sre - pim * sim;
                T2im[i * n + b] = pre * sim + pim * sre;
            }
        }
        for (int a = 0; a < n; a++)
            for (int b = 0; b < n; b++) {
                double gre = 0.0;
                for (int mu = 0; mu < n; mu++)
                    gre += Qre[mu * n + a] * T2re[mu * n + b]
                         + Qim[mu * n + a] * T2im[mu * n + b];
                if (gre < 1e-12 && gre > -1e-12) gre = 0.0;
                g[a * n + b] = gre;
            }
    }
};

__host__ __device__ constexpr double getG(int l, int idx) {
    return GMatT(l).g[idx];
}

template <int L, bool TRANS, int I, int J>
__device__ __forceinline__ float mv_row(const float (&u)[2 * L + 1]) {
    constexpr int n = 2 * L + 1;
    constexpr double gd = getG(L, TRANS ? (J * n + I) : (I * n + J));
    float acc;
    if constexpr (J + 1 < n) acc = mv_row<L, TRANS, I, J + 1>(u);
    else                     acc = 0.0f;
    if constexpr (gd != 0.0) acc = fmaf((float)gd, u[J], acc);
    return acc;
}

template <int L, bool TRANS, int I = 0>
__device__ __forceinline__ void matvec(float (&v)[2 * L + 1],
                                       const float (&u)[2 * L + 1]) {
    v[I] = mv_row<L, TRANS, I, 0>(u);
    if constexpr (I + 1 < 2 * L + 1) matvec<L, TRANS, I + 1>(v, u);
}

// ============================================================================
// Main kernel: out = Yr(a) * G * Yr(-b) * G^T * Yr(g) * s  for l = 4, 6
// R12 structure + gamma normalization removed:
//   M01 = ca*R01 - sa*R21 == 0 by construction and M is orthogonal, so
//   M00^2 + M02^2 = 1 (+-1e-7): cg = M00, sg = M02 directly (no rsqrt).
//   cb clamp dropped (1-cb^2 is floor-guarded).
// ============================================================================
__global__ void __launch_bounds__(128, 12)
wigner_kernel(const float4* __restrict__ quats,
              const float* __restrict__ s4in,
              const float* __restrict__ s6in,
              float* __restrict__ out4,
              float* __restrict__ out6,
              int B)
{
    __shared__ float shs[22];
    __shared__ alignas(16) float stage4[4][288];
    __shared__ alignas(16) float stage6[4][416];

    const int tid = threadIdx.x;
    if (tid < 22) shs[tid] = (tid < 9) ? s4in[tid] : s6in[tid - 9];
    __syncthreads();

    const int warp = tid >> 5, lane = tid & 31;
    const int warpStart = blockIdx.x * 128 + (warp << 5);
    if (warpStart >= B) return;
    const bool full = (warpStart + 32 <= B);
    const int b = warpStart + lane;

    float4 q = (b < B) ? __ldcs(&quats[b]) : make_float4(1.f, 0.f, 0.f, 0.f);
    float w = q.x, x = q.y, y = q.z, z = q.w;
    float c   = 2.f * w * w - 1.f;
    float R01 = 2.f * (x * y - w * z);
    float R11 = c + 2.f * y * y;
    float R21 = 2.f * (y * z + w * x);
    float R00 = c + 2.f * x * x;
    float R02 = 2.f * (x * z + w * y);
    float R20 = 2.f * (x * z - w * y);
    float R22 = c + 2.f * z * z;

    // unit quaternion => middle column already unit-norm
    float cb = R11;
    float sb = sqrtf(fmaxf(0.f, 1.f - cb * cb));
    float ra2 = R01 * R01 + R21 * R21;
    float ca, sa;
    if (ra2 > 1e-20f) { float r = rsqrtf(ra2); ca = R21 * r; sa = R01 * r; }
    else              { ca = 1.f; sa = 0.f; }
    // row 0 of M is (cg, 0, sg) with unit norm: no normalization needed
    float cg = ca * R00 - sa * R20;
    float sg = ca * R02 - sa * R22;

    float* st4 = stage4[warp];
    float* st6 = stage6[warp];

    // ------------------------------- l = 4 --------------------------------
    {
        float u[9], v[9];
        {
            float cp = cg, sp = sg;
            u[4] = shs[4];
#pragma unroll
            for (int p = 1; p <= 4; p++) {
                float a_ = shs[4 + p], b_ = shs[4 - p];
                u[4 + p] = cp * a_ - sp * b_;
                u[4 - p] = sp * a_ + cp * b_;
                if (p < 4) { float cn = cp * cg - sp * sg;
                             sp = sp * cg + cp * sg; cp = cn; }
            }
        }
        matvec<4, true>(v, u);          // v = G^T u
        {
            float cp = cb, sp = sb;
#pragma unroll
            for (int p = 1; p <= 4; p++) {
                float a_ = v[4 + p], b_ = v[4 - p];
                v[4 + p] =  cp * a_ + sp * b_;
                v[4 - p] = -sp * a_ + cp * b_;
                if (p < 4) { float cn = cp * cb - sp * sb;
                             sp = sp * cb + cp * sb; cp = cn; }
            }
        }
        matvec<4, false>(u, v);         // u = G v
        {
            float cp = ca, sp = sa;
            st4[lane * 9 + 4] = u[4];
#pragma unroll
            for (int p = 1; p <= 4; p++) {
                st4[lane * 9 + 4 + p] = cp * u[4 + p] - sp * u[4 - p];
                st4[lane * 9 + 4 - p] = sp * u[4 + p] + cp * u[4 - p];
                if (p < 4) { float cn = cp * ca - sp * sa;
                             sp = sp * ca + cp * sa; cp = cn; }
            }
        }
    }
    __syncwarp();
    if (full) {
        const float4* sv = (const float4*)st4;
        float4* g4 = (float4*)(out4 + (size_t)warpStart * 9);
#pragma unroll
        for (int it = 0; it < 3; it++) {
            int k = lane + 32 * it;
            if (k < 72) __stcs(&g4[k], sv[k]);
        }
    } else {
        int cnt = B - warpStart;
        for (int k = lane; k < cnt * 9; k += 32)
            __stcs(&out4[(size_t)warpStart * 9 + k], st4[k]);
    }

    // ------------------------------- l = 6 --------------------------------
    {
        float u[13], v[13];
        {
            float cp = cg, sp = sg;
            u[6] = shs[9 + 6];
#pragma unroll
            for (int p = 1; p <= 6; p++) {
                float a_ = shs[9 + 6 + p], b_ = shs[9 + 6 - p];
                u[6 + p] = cp * a_ - sp * b_;
                u[6 - p] = sp * a_ + cp * b_;
                if (p < 6) { float cn = cp * cg - sp * sg;
                             sp = sp * cg + cp * sg; cp = cn; }
            }
        }
        matvec<6, true>(v, u);          // v = G^T u
        {
            float cp = cb, sp = sb;
#pragma unroll
            for (int p = 1; p <= 6; p++) {
                float a_ = v[6 + p], b_ = v[6 - p];
                v[6 + p] =  cp * a_ + sp * b_;
                v[6 - p] = -sp * a_ + cp * b_;
                if (p < 6) { float cn = cp * cb - sp * sb;
                             sp = sp * cb + cp * sb; cp = cn; }
            }
        }
        matvec<6, false>(u, v);         // u = G v
        {
            float cp = ca, sp = sa;
            st6[lane * 13 + 6] = u[6];
#pragma unroll
            for (int p = 1; p <= 6; p++) {
                st6[lane * 13 + 6 + p] = cp * u[6 + p] - sp * u[6 - p];
                st6[lane * 13 + 6 - p] = sp * u[6 + p] + cp * u[6 - p];
                if (p < 6) { float cn = cp * ca - sp * sa;
                             sp = sp * ca + cp * sa; cp = cn; }
            }
        }
    }
    __syncwarp();
    {
        bool al6 = ((reinterpret_cast<unsigned long long>(out6) & 15ull) == 0ull);
        if (full && al6) {
            const float4* sv = (const float4*)st6;
            float4* g6 = (float4*)(out6 + (size_t)warpStart * 13);
#pragma unroll
            for (int it = 0; it < 4; it++) {
                int k = lane + 32 * it;
                if (k < 104) __stcs(&g6[k], sv[k]);
            }
        } else {
            int cnt = B - warpStart; if (cnt > 32) cnt = 32;
            for (int k = lane; k < cnt * 13; k += 32)
                __stcs(&out6[(size_t)warpStart * 13 + k], st6[k]);
        }
    }
}

extern "C" void kernel_launch(void* const* d_in, const int* in_sizes, int n_in,
                              void* d_out, int out_size)
{
    const float4* quats = (const float4*)d_in[0];
    const float* s4 = (const float*)d_in[1];
    const float* s6 = (const float*)d_in[2];
    if (n_in >= 3 && in_sizes[1] == 13 && in_sizes[2] == 9) {
        const float* t = s4; s4 = s6; s6 = t;
    }
    const int B = in_sizes[0] / 4;
    float* out  = (float*)d_out;
    float* out4 = out;
    float* out6 = out + (size_t)B * 9;

    const int grid = (B + 127) / 128;
    wigner_kernel<<<grid, 128>>>(quats, s4, s6, out4, out6, B);
}

// round 14
// speedup vs baseline: 1.0548x; 1.0548x over previous
#include <cuda_runtime.h>
#include <cuda_bf16.h>
#include <cstdint>

// ============================================================================
// Compile-time construction of the conjugator matrices
//   G_l = Re(Q^H * P * d(pi/2) * Q)
// Every matrix element becomes a SASS immediate (FFMA src1-imm, rt=1) and
// structural zeros are deleted at compile time.
// ============================================================================

__host__ __device__ constexpr double csqrt_c(double x) {
    if (x <= 0.0) return 0.0;
    double s = 1.0;
    while (x > 4.0)  { x *= 0.25; s *= 2.0; }
    while (x < 0.25) { x *= 4.0;  s *= 0.5; }
    double g = 1.0;
    for (int i = 0; i < 30; i++) g = 0.5 * (g + x / g);
    return s * g;
}

struct GMatT {
    double g[169];
    __host__ __device__ constexpr GMatT(int l) : g{} {
        double fact[14] = {};
        fact[0] = 1.0;
        for (int i = 1; i < 14; i++) fact[i] = fact[i - 1] * (double)i;
        const int n = 2 * l + 1;
        double dmat[169] = {}, Qre[169] = {}, Qim[169] = {};
        double T2re[169] = {}, T2im[169] = {};
        double scale = 1.0;
        for (int i = 0; i < l; i++) scale *= 0.5;   // 2^-l

        for (int i = 0; i < n; i++)
            for (int j = 0; j < n; j++) {
                int mp = i - l, m = j - l;
                double pref = csqrt_c(fact[l + mp] * fact[l - mp] *
                                      fact[l + m] * fact[l - m]);
                int smin = (m - mp > 0) ? (m - mp) : 0;
                int smax = (l + m < l - mp) ? (l + m) : (l - mp);
                double sum = 0.0;
                for (int s = smin; s <= smax; s++) {
                    double term = 1.0 / (fact[l + m - s] * fact[s] *
                                         fact[mp - m + s] * fact[l - mp - s]);
                    sum += ((mp - m + s) & 1) ? -term : term;
                }
                dmat[i * n + j] = pref * sum * scale;
            }
        const double irt2 = 0.70710678118654752440084436210485;
        for (int m = -l; m < 0; m++) {
            Qre[(l + m) * n + (l - m)] = irt2;
            Qim[(l + m) * n + (l + m)] = -irt2;
        }
        Qre[l * n + l] = 1.0;
        for (int m = 1; m <= l; m++) {
            double sgn = (m & 1) ? -1.0 : 1.0;
            Qre[(l + m) * n + (l + m)] = sgn * irt2;
            Qim[(l + m) * n + (l - m)] = sgn * irt2;
        }
        for (int i = 0; i < n; i++) {
            int mp = i - l;
            int ph = ((mp % 4) + 4) % 4;
            double pre = (ph == 0) ? 1.0 : ((ph == 2) ? -1.0 : 0.0);
            double pim = (ph == 1) ? -1.0 : ((ph == 3) ? 1.0 : 0.0);
            for (int b = 0; b < n; b++) {
                double sre = 0.0, sim = 0.0;
                for (int k = 0; k < n; k++) {
                    double t = dmat[i * n + k];
                    sre += t * Qre[k * n + b];
                    sim += t * Qim[k * n + b];
                }
                T2re[i * n + b] = pre * sre - pim * sim;
                T2im[i * n + b] = pre * sim + pim * sre;
            }
        }
        for (int a = 0; a < n; a++)
            for (int b = 0; b < n; b++) {
                double gre = 0.0;
                for (int mu = 0; mu < n; mu++)
                    gre += Qre[mu * n + a] * T2re[mu * n + b]
                         + Qim[mu * n + a] * T2im[mu * n + b];
                if (gre < 1e-12 && gre > -1e-12) gre = 0.0;
                g[a * n + b] = gre;
            }
    }
};

__host__ __device__ constexpr double getG(int l, int idx) {
    return GMatT(l).g[idx];
}

template <int L, bool TRANS, int I, int J>
__device__ __forceinline__ float mv_row(const float (&u)[2 * L + 1]) {
    constexpr int n = 2 * L + 1;
    constexpr double gd = getG(L, TRANS ? (J * n + I) : (I * n + J));
    float acc;
    if constexpr (J + 1 < n) acc = mv_row<L, TRANS, I, J + 1>(u);
    else                     acc = 0.0f;
    if constexpr (gd != 0.0) acc = fmaf((float)gd, u[J], acc);
    return acc;
}

template <int L, bool TRANS, int I = 0>
__device__ __forceinline__ void matvec(float (&v)[2 * L + 1],
                                       const float (&u)[2 * L + 1]) {
    v[I] = mv_row<L, TRANS, I, 0>(u);
    if constexpr (I + 1 < 2 * L + 1) matvec<L, TRANS, I + 1>(v, u);
}

// ============================================================================
// Main kernel: out = Yr(a) * G * Yr(-b) * G^T * Yr(g) * s  for l = 4, 6
// R13 base + SECOND-ORDER Chebyshev recurrence for the angle multiples:
//   c_{p+1} = 2c * c_p - c_{p-1}  (2 FFMA/step instead of 4 ops/step)
// tested in isolation this time (same launch bounds, same staging).
// ============================================================================
__global__ void __launch_bounds__(128, 12)
wigner_kernel(const float4* __restrict__ quats,
              const float* __restrict__ s4in,
              const float* __restrict__ s6in,
              float* __restrict__ out4,
              float* __restrict__ out6,
              int B)
{
    __shared__ float shs[22];
    __shared__ alignas(16) float stage4[4][288];
    __shared__ alignas(16) float stage6[4][416];

    const int tid = threadIdx.x;
    if (tid < 22) shs[tid] = (tid < 9) ? s4in[tid] : s6in[tid - 9];
    __syncthreads();

    const int warp = tid >> 5, lane = tid & 31;
    const int warpStart = blockIdx.x * 128 + (warp << 5);
    if (warpStart >= B) return;
    const bool full = (warpStart + 32 <= B);
    const int b = warpStart + lane;

    float4 q = (b < B) ? __ldcs(&quats[b]) : make_float4(1.f, 0.f, 0.f, 0.f);
    float w = q.x, x = q.y, y = q.z, z = q.w;
    float c   = 2.f * w * w - 1.f;
    float R01 = 2.f * (x * y - w * z);
    float R11 = c + 2.f * y * y;
    float R21 = 2.f * (y * z + w * x);
    float R00 = c + 2.f * x * x;
    float R02 = 2.f * (x * z + w * y);
    float R20 = 2.f * (x * z - w * y);
    float R22 = c + 2.f * z * z;

    // unit quaternion => middle column already unit-norm
    float cb = R11;
    float sb = sqrtf(fmaxf(0.f, 1.f - cb * cb));
    float ra2 = R01 * R01 + R21 * R21;
    float ca, sa;
    if (ra2 > 1e-20f) { float r = rsqrtf(ra2); ca = R21 * r; sa = R01 * r; }
    else              { ca = 1.f; sa = 0.f; }
    // row 0 of M is (cg, 0, sg) with unit norm: no normalization needed
    float cg = ca * R00 - sa * R20;
    float sg = ca * R02 - sa * R22;

    const float t2a = ca + ca, t2b = cb + cb, t2g = cg + cg;
    float* st4 = stage4[warp];
    float* st6 = stage6[warp];

    // ------------------------------- l = 4 --------------------------------
    {
        float u[9], v[9];
        {
            float cp = cg, sp = sg, cpp = 1.f, spp = 0.f;
            u[4] = shs[4];
#pragma unroll
            for (int p = 1; p <= 4; p++) {
                float a_ = shs[4 + p], b_ = shs[4 - p];
                u[4 + p] = cp * a_ - sp * b_;
                u[4 - p] = sp * a_ + cp * b_;
                if (p < 4) {
                    float cn = fmaf(t2g, cp, -cpp);
                    float sn = fmaf(t2g, sp, -spp);
                    cpp = cp; spp = sp; cp = cn; sp = sn;
                }
            }
        }
        matvec<4, true>(v, u);          // v = G^T u
        {
            float cp = cb, sp = sb, cpp = 1.f, spp = 0.f;
#pragma unroll
            for (int p = 1; p <= 4; p++) {
                float a_ = v[4 + p], b_ = v[4 - p];
                v[4 + p] =  cp * a_ + sp * b_;
                v[4 - p] = -sp * a_ + cp * b_;
                if (p < 4) {
                    float cn = fmaf(t2b, cp, -cpp);
                    float sn = fmaf(t2b, sp, -spp);
                    cpp = cp; spp = sp; cp = cn; sp = sn;
                }
            }
        }
        matvec<4, false>(u, v);         // u = G v
        {
            float cp = ca, sp = sa, cpp = 1.f, spp = 0.f;
            st4[lane * 9 + 4] = u[4];
#pragma unroll
            for (int p = 1; p <= 4; p++) {
                st4[lane * 9 + 4 + p] = cp * u[4 + p] - sp * u[4 - p];
                st4[lane * 9 + 4 - p] = sp * u[4 + p] + cp * u[4 - p];
                if (p < 4) {
                    float cn = fmaf(t2a, cp, -cpp);
                    float sn = fmaf(t2a, sp, -spp);
                    cpp = cp; spp = sp; cp = cn; sp = sn;
                }
            }
        }
    }
    __syncwarp();
    if (full) {
        const float4* sv = (const float4*)st4;
        float4* g4 = (float4*)(out4 + (size_t)warpStart * 9);
#pragma unroll
        for (int it = 0; it < 3; it++) {
            int k = lane + 32 * it;
            if (k < 72) __stcs(&g4[k], sv[k]);
        }
    } else {
        int cnt = B - warpStart;
        for (int k = lane; k < cnt * 9; k += 32)
            __stcs(&out4[(size_t)warpStart * 9 + k], st4[k]);
    }

    // ------------------------------- l = 6 --------------------------------
    {
        float u[13], v[13];
        {
            float cp = cg, sp = sg, cpp = 1.f, spp = 0.f;
            u[6] = shs[9 + 6];
#pragma unroll
            for (int p = 1; p <= 6; p++) {
                float a_ = shs[9 + 6 + p], b_ = shs[9 + 6 - p];
                u[6 + p] = cp * a_ - sp * b_;
                u[6 - p] = sp * a_ + cp * b_;
                if (p < 6) {
                    float cn = fmaf(t2g, cp, -cpp);
                    float sn = fmaf(t2g, sp, -spp);
                    cpp = cp; spp = sp; cp = cn; sp = sn;
                }
            }
        }
        matvec<6, true>(v, u);          // v = G^T u
        {
            float cp = cb, sp = sb, cpp = 1.f, spp = 0.f;
#pragma unroll
            for (int p = 1; p <= 6; p++) {
                float a_ = v[6 + p], b_ = v[6 - p];
                v[6 + p] =  cp * a_ + sp * b_;
                v[6 - p] = -sp * a_ + cp * b_;
                if (p < 6) {
                    float cn = fmaf(t2b, cp, -cpp);
                    float sn = fmaf(t2b, sp, -spp);
                    cpp = cp; spp = sp; cp = cn; sp = sn;
                }
            }
        }
        matvec<6, false>(u, v);         // u = G v
        {
            float cp = ca, sp = sa, cpp = 1.f, spp = 0.f;
            st6[lane * 13 + 6] = u[6];
#pragma unroll
            for (int p = 1; p <= 6; p++) {
                st6[lane * 13 + 6 + p] = cp * u[6 + p] - sp * u[6 - p];
                st6[lane * 13 + 6 - p] = sp * u[6 + p] + cp * u[6 - p];
                if (p < 6) {
                    float cn = fmaf(t2a, cp, -cpp);
                    float sn = fmaf(t2a, sp, -spp);
                    cpp = cp; spp = sp; cp = cn; sp = sn;
                }
            }
        }
    }
    __syncwarp();
    {
        bool al6 = ((reinterpret_cast<unsigned long long>(out6) & 15ull) == 0ull);
        if (full && al6) {
            const float4* sv = (const float4*)st6;
            float4* g6 = (float4*)(out6 + (size_t)warpStart * 13);
#pragma unroll
            for (int it = 0; it < 4; it++) {
                int k = lane + 32 * it;
                if (k < 104) __stcs(&g6[k], sv[k]);
            }
        } else {
            int cnt = B - warpStart; if (cnt > 32) cnt = 32;
            for (int k = lane; k < cnt * 13; k += 32)
                __stcs(&out6[(size_t)warpStart * 13 + k], st6[k]);
        }
    }
}

extern "C" void kernel_launch(void* const* d_in, const int* in_sizes, int n_in,
                              void* d_out, int out_size)
{
    const float4* quats = (const float4*)d_in[0];
    const float* s4 = (const float*)d_in[1];
    const float* s6 = (const float*)d_in[2];
    if (n_in >= 3 && in_sizes[1] == 13 && in_sizes[2] == 9) {
        const float* t = s4; s4 = s6; s6 = t;
    }
    const int B = in_sizes[0] / 4;
    float* out  = (float*)d_out;
    float* out4 = out;
    float* out6 = out + (size_t)B * 9;

    const int grid = (B + 127) / 128;
    wigner_kernel<<<grid, 128>>>(quats, s4, s6, out4, out6, B);
}